// round 3
// baseline (speedup 1.0000x reference)
#include <cuda_runtime.h>

#define D 128
#define NMAX 50048
#define EMAX 1000000

// Scratch (__device__ globals — allocation-free rule)
__device__ float g_h[NMAX * D];      // h' = dis[r] * (x @ W^T + b)[r]
__device__ float g_dis[NMAX];        // (deg+1)^-0.5
__device__ int   g_degi[NMAX];       // edge count per source
__device__ int   g_cnt[NMAX];        // edge count per target
__device__ int   g_off[NMAX + 1];    // CSR offsets (by target)
__device__ int   g_cur[NMAX];        // fill cursors
__device__ int   g_src[EMAX];        // CSR payload: source index per edge

// ---------------------------------------------------------------------------
__global__ void k_zero(int n) {
    int i = blockIdx.x * blockDim.x + threadIdx.x;
    if (i < n) { g_degi[i] = 0; g_cnt[i] = 0; }
}

// histogram both endpoints (edge_index is int32!)
__global__ void k_count(const int* __restrict__ ei, int E) {
    int e = blockIdx.x * blockDim.x + threadIdx.x;
    if (e >= E) return;
    atomicAdd(&g_degi[ei[e]], 1);      // source (deg for norm)
    atomicAdd(&g_cnt[ei[E + e]], 1);   // target (CSR)
}

__global__ void k_dis(int n) {
    int i = blockIdx.x * blockDim.x + threadIdx.x;
    if (i < n) g_dis[i] = rsqrtf((float)(g_degi[i] + 1));  // +1 self loop
}

// single-block exclusive scan of g_cnt -> g_off, g_cur
__global__ void k_scan(int n) {
    __shared__ int sums[1024];
    int t = threadIdx.x;
    int chunk = (n + 1023) >> 10;
    int lo = t * chunk, hi = min(lo + chunk, n);
    int s = 0;
    for (int i = lo; i < hi; i++) s += g_cnt[i];
    sums[t] = s;
    __syncthreads();
    for (int off = 1; off < 1024; off <<= 1) {
        int v = (t >= off) ? sums[t - off] : 0;
        __syncthreads();
        sums[t] += v;
        __syncthreads();
    }
    int base = (t == 0) ? 0 : sums[t - 1];
    for (int i = lo; i < hi; i++) {
        g_off[i] = base;
        g_cur[i] = base;
        base += g_cnt[i];
    }
    if (t == 1023) g_off[n] = base;
}

// bin edges into CSR by target
__global__ void k_fill(const int* __restrict__ ei, int E) {
    int e = blockIdx.x * blockDim.x + threadIdx.x;
    if (e >= E) return;
    int r = ei[e];
    int c = ei[E + e];
    int pos = atomicAdd(&g_cur[c], 1);
    g_src[pos] = r;
}

// ---------------------------------------------------------------------------
// GEMM: g_h[r][c] = dis[r] * (sum_k x[r][k]*W[c][k] + b[c])
// 256 threads, 64 rows x 128 cols per block. W transposed in smem.
__global__ void k_gemm(const float* __restrict__ x, const float* __restrict__ W,
                       const float* __restrict__ b, int n) {
    extern __shared__ float sm[];
    float* Ws = sm;            // [128][128], Ws[k][c] = W[c][k]
    float* xs = sm + D * D;    // [64][128]
    int t = threadIdx.x;

    for (int i = t; i < (D * D) / 4; i += 256) {
        int c = i & 127;
        int k4 = (i >> 7) * 4;
        float4 w = *(const float4*)&W[c * D + k4];
        Ws[(k4 + 0) * D + c] = w.x;
        Ws[(k4 + 1) * D + c] = w.y;
        Ws[(k4 + 2) * D + c] = w.z;
        Ws[(k4 + 3) * D + c] = w.w;
    }

    int row0 = blockIdx.x * 64;
    int nrows = min(64, n - row0);
    for (int i = t; i < nrows * 32; i += 256) {
        int r = i >> 5;
        int k4 = (i & 31) * 4;
        *(float4*)&xs[r * D + k4] = *(const float4*)&x[(row0 + r) * D + k4];
    }
    __syncthreads();

    int c4 = (t & 31) * 4;
    int r8 = (t >> 5) * 8;

    float4 acc[8];
#pragma unroll
    for (int r = 0; r < 8; r++) acc[r] = make_float4(0.f, 0.f, 0.f, 0.f);

#pragma unroll 4
    for (int k = 0; k < D; k++) {
        float4 w = *(float4*)&Ws[k * D + c4];
#pragma unroll
        for (int r = 0; r < 8; r++) {
            float xv = xs[(r8 + r) * D + k];
            acc[r].x += xv * w.x;
            acc[r].y += xv * w.y;
            acc[r].z += xv * w.z;
            acc[r].w += xv * w.w;
        }
    }

    float4 bv = *(const float4*)&b[c4];
#pragma unroll
    for (int r = 0; r < 8; r++) {
        int row = row0 + r8 + r;
        if (row < n) {
            float dv = g_dis[row];
            float4 o;
            o.x = (acc[r].x + bv.x) * dv;
            o.y = (acc[r].y + bv.y) * dv;
            o.z = (acc[r].z + bv.z) * dv;
            o.w = (acc[r].w + bv.w) * dv;
            *(float4*)&g_h[row * D + c4] = o;
        }
    }
}

// ---------------------------------------------------------------------------
// Fused gather + self-loop + ReLU + LayerNorm + residual. Warp per node.
__global__ void k_agg(const float* __restrict__ x,
                      const float* __restrict__ gamma,
                      const float* __restrict__ beta,
                      float* __restrict__ out, int n) {
    int node = (blockIdx.x * blockDim.x + threadIdx.x) >> 5;
    int lane = threadIdx.x & 31;
    if (node >= n) return;

    float dc = g_dis[node];
    int lo = g_off[node], hi = g_off[node + 1];

    float4 acc = make_float4(0.f, 0.f, 0.f, 0.f);
    for (int i = lo; i < hi; i++) {
        int r = g_src[i];  // lane-uniform (warp-broadcast load)
        float4 m = *(const float4*)&g_h[r * D + lane * 4];
        acc.x += m.x; acc.y += m.y; acc.z += m.z; acc.w += m.w;
    }
    // self loop: adds h'[c]; final scale by dis[c] gives dis[c]^2 * h[c]
    float4 hs = *(const float4*)&g_h[node * D + lane * 4];
    acc.x += hs.x; acc.y += hs.y; acc.z += hs.z; acc.w += hs.w;

    float4 v;
    v.x = fmaxf(acc.x * dc, 0.f);
    v.y = fmaxf(acc.y * dc, 0.f);
    v.z = fmaxf(acc.z * dc, 0.f);
    v.w = fmaxf(acc.w * dc, 0.f);

    float s  = v.x + v.y + v.z + v.w;
    float ss = v.x * v.x + v.y * v.y + v.z * v.z + v.w * v.w;
#pragma unroll
    for (int o = 16; o; o >>= 1) {
        s  += __shfl_xor_sync(0xffffffffu, s,  o);
        ss += __shfl_xor_sync(0xffffffffu, ss, o);
    }
    float mu  = s * (1.f / 128.f);
    float var = ss * (1.f / 128.f) - mu * mu;
    float inv = rsqrtf(var + 1e-5f);

    float4 g  = *(const float4*)&gamma[lane * 4];
    float4 be = *(const float4*)&beta[lane * 4];
    float4 xv = *(const float4*)&x[node * D + lane * 4];

    float4 o;
    o.x = (v.x - mu) * inv * g.x + be.x + xv.x;
    o.y = (v.y - mu) * inv * g.y + be.y + xv.y;
    o.z = (v.z - mu) * inv * g.z + be.z + xv.z;
    o.w = (v.w - mu) * inv * g.w + be.w + xv.w;
    *(float4*)&out[node * D + lane * 4] = o;
}

// ---------------------------------------------------------------------------
extern "C" void kernel_launch(void* const* d_in, const int* in_sizes, int n_in,
                              void* d_out, int out_size) {
    const float* x     = (const float*)d_in[0];
    const int*   ei    = (const int*)d_in[1];    // int32! (JAX x64 disabled)
    const float* W     = (const float*)d_in[2];
    const float* b     = (const float*)d_in[3];
    const float* gamma = (const float*)d_in[4];
    const float* beta  = (const float*)d_in[5];
    float*       out   = (float*)d_out;

    int n = in_sizes[0] / D;
    int E = in_sizes[1] / 2;

    k_zero<<<(n + 255) / 256, 256>>>(n);
    k_count<<<(E + 255) / 256, 256>>>(ei, E);
    k_dis<<<(n + 255) / 256, 256>>>(n);

    int smem = (D * D + 64 * D) * sizeof(float);  // 96 KB
    cudaFuncSetAttribute(k_gemm, cudaFuncAttributeMaxDynamicSharedMemorySize, smem);
    k_gemm<<<(n + 63) / 64, 256, smem>>>(x, W, b, n);

    k_scan<<<1, 1024>>>(n);
    k_fill<<<(E + 255) / 256, 256>>>(ei, E);

    k_agg<<<(n + 7) / 8, 256>>>(x, gamma, beta, out, n);
}